// round 8
// baseline (speedup 1.0000x reference)
#include <cuda_runtime.h>

// Problem constants (fixed by reference setup_inputs):
//   img : (1, 64, 64, 1024) float32
//   rois: (1, 1024, 4) int32  [x, y, w, h]
//   out : (1, 1024, 7, 7, 1024) float32
#define IMG_W    64
#define CHAN     1024
#define POOLP    7
#define C4       (CHAN / 4)        // 256 float4 per pixel
#define ROWF4    (IMG_W * C4)      // float4 stride of one image row

// One block per (roi, px) column. Each thread owns one float4 channel slice
// and walks the 7 pooled rows, caching up to 2 horizontally-lerped source
// rows in registers (row indices are monotone in py, so 2-slot LRU captures
// all reuse). All cache tags/branches are block-uniform -> no divergence.
__global__ __launch_bounds__(256, 4)
void roi_bilinear_cols_kernel(const float* __restrict__ img,
                              const int*   __restrict__ rois,
                              float*       __restrict__ out)
{
    const int blk = blockIdx.x;        // 0 .. R*7-1
    const int r   = blk / POOLP;       // roi index
    const int px  = blk % POOLP;       // pooled column

    const int4 roi = __ldg(((const int4*)rois) + r);
    const int rx = roi.x, ry = roi.y, rw = roi.z, rh = roi.w;

    // ---- x axis (block-uniform) ----
    const float scx  = (float)rw * (1.0f / (float)POOLP);
    const float srcx = ((float)px + 0.5f) * scx - 0.5f;
    const float fx   = floorf(srcx);
    const float tx   = srcx - fx;
    const int   ix   = (int)fx;
    const int   x0   = rx + min(max(ix,     0), rw - 1);
    const int   x1   = rx + min(max(ix + 1, 0), rw - 1);
    const float w0x  = 1.0f - tx;
    const float w1x  = tx;

    // y scale (block-uniform)
    const float scy = (float)rh * (1.0f / (float)POOLP);

    const int c = threadIdx.x;  // channel float4 slice

    // Column base pointers: add y*ROWF4 per source row.
    const float4* p0 = (const float4*)img + (size_t)x0 * C4 + c;
    const float4* p1 = (const float4*)img + (size_t)x1 * C4 + c;
    float4* dst = (float4*)out + ((size_t)r * (POOLP * POOLP) + px) * C4 + c;

    // 2-slot register cache of h-lerped rows (tags block-uniform).
    int   cy0 = -1, cy1 = -1;
    float4 ch0, ch1;
    bool  evict0 = true;

    #pragma unroll
    for (int py = 0; py < POOLP; ++py) {
        const float srcy = ((float)py + 0.5f) * scy - 0.5f;
        const float fy   = floorf(srcy);
        const float ty   = srcy - fy;
        const int   iy   = (int)fy;
        const int   y0   = ry + min(max(iy,     0), rh - 1);
        const int   y1   = ry + min(max(iy + 1, 0), rh - 1);

        float4 top, bot;

        // fetch row y0
        if (y0 == cy0)      { top = ch0; evict0 = false; }
        else if (y0 == cy1) { top = ch1; evict0 = true;  }
        else {
            const float4 a = __ldg(p0 + (size_t)y0 * ROWF4);
            const float4 b = __ldg(p1 + (size_t)y0 * ROWF4);
            top.x = fmaf(b.x, w1x, a.x * w0x);
            top.y = fmaf(b.y, w1x, a.y * w0x);
            top.z = fmaf(b.z, w1x, a.z * w0x);
            top.w = fmaf(b.w, w1x, a.w * w0x);
            if (evict0) { ch0 = top; cy0 = y0; evict0 = false; }
            else        { ch1 = top; cy1 = y0; evict0 = true;  }
        }

        // fetch row y1
        if (y1 == cy0)      { bot = ch0; evict0 = false; }
        else if (y1 == cy1) { bot = ch1; evict0 = true;  }
        else {
            const float4 a = __ldg(p0 + (size_t)y1 * ROWF4);
            const float4 b = __ldg(p1 + (size_t)y1 * ROWF4);
            bot.x = fmaf(b.x, w1x, a.x * w0x);
            bot.y = fmaf(b.y, w1x, a.y * w0x);
            bot.z = fmaf(b.z, w1x, a.z * w0x);
            bot.w = fmaf(b.w, w1x, a.w * w0x);
            if (evict0) { ch0 = bot; cy0 = y1; evict0 = false; }
            else        { ch1 = bot; cy1 = y1; evict0 = true;  }
        }

        // vertical lerp (matches reference: top*(1-ty) + bot*ty)
        const float w0y = 1.0f - ty;
        const float w1y = ty;
        float4 o;
        o.x = fmaf(bot.x, w1y, top.x * w0y);
        o.y = fmaf(bot.y, w1y, top.y * w0y);
        o.z = fmaf(bot.z, w1y, top.z * w0y);
        o.w = fmaf(bot.w, w1y, top.w * w0y);

        dst[(size_t)py * (POOLP * C4)] = o;
    }
}

extern "C" void kernel_launch(void* const* d_in, const int* in_sizes, int n_in,
                              void* d_out, int out_size)
{
    const float* img  = (const float*)d_in[0];
    const int*   rois = (const int*)  d_in[1];
    float*       out  = (float*)d_out;

    const int R = in_sizes[1] / 4;       // 1024 rois
    const int nblocks = R * POOLP;       // 7168 blocks, one per (roi, px)

    roi_bilinear_cols_kernel<<<nblocks, 256>>>(img, rois, out);
}

// round 9
// speedup vs baseline: 1.0141x; 1.0141x over previous
#include <cuda_runtime.h>

// Problem constants (fixed by reference setup_inputs):
//   img : (1, 64, 64, 1024) float32
//   rois: (1, 1024, 4) int32  [x, y, w, h]
//   out : (1, 1024, 7, 7, 1024) float32
#define IMG_W    64
#define CHAN     1024
#define POOLP    7
#define C4       (CHAN / 4)        // 256 float4 per pixel
#define ROWF4    (IMG_W * C4)      // float4 stride of one image row

// One block per (roi, px) column. Each thread owns one float4 channel slice
// and walks the 7 pooled rows, caching up to 2 horizontally-lerped source
// rows in registers (row indices are monotone in py, so 2-slot LRU captures
// all reuse). All cache tags/branches are block-uniform -> no divergence.
__global__ __launch_bounds__(256, 4)
void roi_bilinear_cols_kernel(const float* __restrict__ img,
                              const int*   __restrict__ rois,
                              float*       __restrict__ out)
{
    const int blk = blockIdx.x;        // 0 .. R*7-1
    const int r   = blk / POOLP;       // roi index
    const int px  = blk % POOLP;       // pooled column

    const int4 roi = __ldg(((const int4*)rois) + r);
    const int rx = roi.x, ry = roi.y, rw = roi.z, rh = roi.w;

    // ---- x axis (block-uniform) ----
    const float scx  = (float)rw * (1.0f / (float)POOLP);
    const float srcx = ((float)px + 0.5f) * scx - 0.5f;
    const float fx   = floorf(srcx);
    const float tx   = srcx - fx;
    const int   ix   = (int)fx;
    const int   x0   = rx + min(max(ix,     0), rw - 1);
    const int   x1   = rx + min(max(ix + 1, 0), rw - 1);
    const float w0x  = 1.0f - tx;
    const float w1x  = tx;

    // y scale (block-uniform)
    const float scy = (float)rh * (1.0f / (float)POOLP);

    const int c = threadIdx.x;  // channel float4 slice

    // Column base pointers: add y*ROWF4 per source row.
    const float4* p0 = (const float4*)img + (size_t)x0 * C4 + c;
    const float4* p1 = (const float4*)img + (size_t)x1 * C4 + c;
    float4* dst = (float4*)out + ((size_t)r * (POOLP * POOLP) + px) * C4 + c;

    // 2-slot register cache of h-lerped rows (tags block-uniform).
    int   cy0 = -1, cy1 = -1;
    float4 ch0, ch1;
    bool  evict0 = true;

    #pragma unroll
    for (int py = 0; py < POOLP; ++py) {
        const float srcy = ((float)py + 0.5f) * scy - 0.5f;
        const float fy   = floorf(srcy);
        const float ty   = srcy - fy;
        const int   iy   = (int)fy;
        const int   y0   = ry + min(max(iy,     0), rh - 1);
        const int   y1   = ry + min(max(iy + 1, 0), rh - 1);

        float4 top, bot;

        // fetch row y0
        if (y0 == cy0)      { top = ch0; evict0 = false; }
        else if (y0 == cy1) { top = ch1; evict0 = true;  }
        else {
            const float4 a = __ldg(p0 + (size_t)y0 * ROWF4);
            const float4 b = __ldg(p1 + (size_t)y0 * ROWF4);
            top.x = fmaf(b.x, w1x, a.x * w0x);
            top.y = fmaf(b.y, w1x, a.y * w0x);
            top.z = fmaf(b.z, w1x, a.z * w0x);
            top.w = fmaf(b.w, w1x, a.w * w0x);
            if (evict0) { ch0 = top; cy0 = y0; evict0 = false; }
            else        { ch1 = top; cy1 = y0; evict0 = true;  }
        }

        // fetch row y1
        if (y1 == cy0)      { bot = ch0; evict0 = false; }
        else if (y1 == cy1) { bot = ch1; evict0 = true;  }
        else {
            const float4 a = __ldg(p0 + (size_t)y1 * ROWF4);
            const float4 b = __ldg(p1 + (size_t)y1 * ROWF4);
            bot.x = fmaf(b.x, w1x, a.x * w0x);
            bot.y = fmaf(b.y, w1x, a.y * w0x);
            bot.z = fmaf(b.z, w1x, a.z * w0x);
            bot.w = fmaf(b.w, w1x, a.w * w0x);
            if (evict0) { ch0 = bot; cy0 = y1; evict0 = false; }
            else        { ch1 = bot; cy1 = y1; evict0 = true;  }
        }

        // vertical lerp (matches reference: top*(1-ty) + bot*ty)
        const float w0y = 1.0f - ty;
        const float w1y = ty;
        float4 o;
        o.x = fmaf(bot.x, w1y, top.x * w0y);
        o.y = fmaf(bot.y, w1y, top.y * w0y);
        o.z = fmaf(bot.z, w1y, top.z * w0y);
        o.w = fmaf(bot.w, w1y, top.w * w0y);

        dst[(size_t)py * (POOLP * C4)] = o;
    }
}

extern "C" void kernel_launch(void* const* d_in, const int* in_sizes, int n_in,
                              void* d_out, int out_size)
{
    const float* img  = (const float*)d_in[0];
    const int*   rois = (const int*)  d_in[1];
    float*       out  = (float*)d_out;

    const int R = in_sizes[1] / 4;       // 1024 rois
    const int nblocks = R * POOLP;       // 7168 blocks, one per (roi, px)

    roi_bilinear_cols_kernel<<<nblocks, 256>>>(img, rois, out);
}